// round 16
// baseline (speedup 1.0000x reference)
#include <cuda_runtime.h>
#include <cuda_fp16.h>
#include <math.h>
#include <stdint.h>

#define B    16
#define C    128
#define HH   128
#define WW   128
#define HW   (HH*WW)
#define KK   9
#define KCH  16
#define NCHUNK (C/KCH)     // 8
#define SBST 72            // sB row stride in halves (64 + 8 pad)

// Scratch
__device__ __half g_wh[C*C];               // conv weights fp16 [o][k]
__device__ float  g_att[B*C];              // CA attention
__device__ float  g_t[B*C];                // hidden MLP activations
__device__ float  g_hid[B*16];             // CA hidden activations
__device__ float  g_kern[B*C*KK];          // per-(b,c) 3x3 kernels

__device__ __forceinline__ float lrelu(float v) { return v > 0.f ? v : 0.1f*v; }

__device__ __forceinline__ void cp16(void* dst, const void* src) {
    uint32_t d = (uint32_t)__cvta_generic_to_shared(dst);
    asm volatile("cp.async.cg.shared.global [%0], [%1], 16;" :: "r"(d), "l"(src));
}
__device__ __forceinline__ void cp_commit() {
    asm volatile("cp.async.commit_group;");
}

__device__ __forceinline__ void ldmatrix_x4(uint32_t* r, const void* p) {
    uint32_t a = (uint32_t)__cvta_generic_to_shared(p);
    asm volatile("ldmatrix.sync.aligned.m8n8.x4.shared.b16 {%0,%1,%2,%3}, [%4];"
                 : "=r"(r[0]), "=r"(r[1]), "=r"(r[2]), "=r"(r[3]) : "r"(a));
}
__device__ __forceinline__ void ldmatrix_x2_t(uint32_t* r, const void* p) {
    uint32_t a = (uint32_t)__cvta_generic_to_shared(p);
    asm volatile("ldmatrix.sync.aligned.m8n8.x2.trans.shared.b16 {%0,%1}, [%2];"
                 : "=r"(r[0]), "=r"(r[1]) : "r"(a));
}
__device__ __forceinline__ void mma_f16(float* d, const uint32_t* a, const uint32_t* b) {
    asm volatile(
        "mma.sync.aligned.m16n8k16.row.col.f32.f16.f16.f32 "
        "{%0,%1,%2,%3}, {%4,%5,%6,%7}, {%8,%9}, {%0,%1,%2,%3};"
        : "+f"(d[0]), "+f"(d[1]), "+f"(d[2]), "+f"(d[3])
        : "r"(a[0]), "r"(a[1]), "r"(a[2]), "r"(a[3]), "r"(b[0]), "r"(b[1]));
}

// ---------------------------------------------------------------------------
// P1: one block per MLP output j (144). grid = 144, block = 256.
// ---------------------------------------------------------------------------
__global__ void prep1_kernel(const float* __restrict__ deg,
                             const float* __restrict__ w1,
                             const float* __restrict__ caw1)
{
    const int j    = blockIdx.x;
    const int tid  = threadIdx.x;
    const int wid  = tid >> 5;
    const int lane = tid & 31;

    __shared__ float sdeg[B][C];

    #pragma unroll
    for (int i = tid; i < B*C; i += 256)
        ((float*)sdeg)[i] = deg[i];
    __syncthreads();

    const float* wrow = (j < 128) ? (w1 + j*C) : (caw1 + (j-128)*C);
    float w[4];
    #pragma unroll
    for (int u = 0; u < 4; ++u) w[u] = wrow[lane*4 + u];

    #pragma unroll
    for (int rep = 0; rep < 2; ++rep) {
        const int b = wid + rep*8;
        float acc = 0.f;
        #pragma unroll
        for (int u = 0; u < 4; ++u) acc += sdeg[b][lane*4 + u]*w[u];
        #pragma unroll
        for (int s = 16; s > 0; s >>= 1) acc += __shfl_xor_sync(0xffffffffu, acc, s);
        if (lane == 0) {
            if (j < 128) g_t[b*C + j]        = lrelu(acc);
            else         g_hid[b*16 + j-128] = lrelu(acc);
        }
    }
}

// ---------------------------------------------------------------------------
// P1b: CA attention sigmoid + fp16 weight conversion. grid = B, block = 256.
// ---------------------------------------------------------------------------
__global__ void prep1b_kernel(const float* __restrict__ caw2,
                              const float* __restrict__ convw)
{
    const int b   = blockIdx.x;
    const int tid = threadIdx.x;

    __shared__ float shid[16];
    if (tid < 16) shid[tid] = g_hid[b*16 + tid];
    __syncthreads();

    if (tid < C) {
        float acc = 0.f;
        const float* wrow = caw2 + tid*16;
        #pragma unroll
        for (int r = 0; r < 16; ++r) acc += shid[r]*wrow[r];
        g_att[b*C + tid] = 1.f/(1.f + expf(-acc));
    }

    {
        const int base = b*1024 + tid*4;
        float4 v = *(const float4*)(convw + base);
        g_wh[base+0] = __float2half(v.x);
        g_wh[base+1] = __float2half(v.y);
        g_wh[base+2] = __float2half(v.z);
        g_wh[base+3] = __float2half(v.w);
    }
}

// ---------------------------------------------------------------------------
// P2: kernel coefficients, one warp per output (B*C*KK = 18432 dots of 128).
// grid = 2304, block = 256.
// ---------------------------------------------------------------------------
__global__ void prep2_kernel(const float* __restrict__ w2)
{
    const int wid  = threadIdx.x >> 5;
    const int lane = threadIdx.x & 31;
    const int j    = blockIdx.x*8 + wid;
    const int b    = j / (C*KK);
    const int j2   = j - b*(C*KK);

    const float* trow = g_t + b*C;
    const float* wrow = w2 + (size_t)j2*C;

    float acc = 0.f;
    #pragma unroll
    for (int i = 0; i < 4; ++i) {
        const int idx = lane*4 + i;
        acc += trow[idx]*wrow[idx];
    }
    #pragma unroll
    for (int s = 16; s > 0; s >>= 1) acc += __shfl_xor_sync(0xffffffffu, acc, s);
    if (lane == 0) g_kern[(size_t)b*C*KK + j2] = acc;
}

// ---------------------------------------------------------------------------
// FUSED kernel: dwconv producer + fp16 MMA + epilogue, no mid buffer.
// Block = (b, h, half): M=128(o) x N=64(px). 8 warps (4M x 2N), warp 32x32.
// K=128 in 8 chunks of 16 channels. Producer prefetches chunk c+1's x0 rows
// (registers) before chunk c's MMAs. sA = full 32 KB weights (cp.async once,
// XOR swizzle from R8); sB = 2-stage 16x72-half tile.
// grid = (HH*2, B), block = 256.
// ---------------------------------------------------------------------------
__global__ void __launch_bounds__(256, 2)
fused_kernel(const float* __restrict__ bias,
             const float* __restrict__ x0,
             float* __restrict__ out)
{
    __shared__ __align__(16) __half sA[C*128];        // 32 KB, swizzled
    __shared__ __align__(16) __half sB[2][KCH*SBST];  // 2 x 2304 B

    const int b    = blockIdx.y;
    const int h    = blockIdx.x >> 1;
    const int px0  = (blockIdx.x & 1) * 64;
    const int tid  = threadIdx.x;
    const int wid  = tid >> 5;
    const int lane = tid & 31;
    const int g    = lane >> 2;
    const int tg   = lane & 3;
    const int wm0  = (wid >> 1) * 32;   // 4 M groups of 32
    const int wn0  = (wid & 1) * 32;    // 2 N groups of 32

    float d[2][4][4];
    #pragma unroll
    for (int mt = 0; mt < 2; ++mt)
        #pragma unroll
        for (int nt = 0; nt < 4; ++nt)
            #pragma unroll
            for (int r = 0; r < 4; ++r) d[mt][nt][r] = 0.f;

    // ---- issue sA load (full K) asynchronously ----
    {
        const int ao = tid >> 1;
        const int ub = (tid & 1) * 8;
        const __half* srca = g_wh + ao*C;
        __half* dsta = &sA[ao*128];
        #pragma unroll
        for (int i = 0; i < 8; ++i) {
            const int u = ub + i;
            cp16(dsta + ((u ^ (ao & 7)) << 3), srca + u*8);
        }
        cp_commit();
    }

    // ---- producer state ----
    const int pch = tid >> 4;            // channel within chunk (0..15)
    const int w0  = px0 + (tid & 15)*4;  // absolute column of 4-px segment
    float4 v4[3]; float vl[3], vr[3];
    float kv[9];
    uint2 pk;

#define LOADX(cc) do {                                                         \
        const int gc = (cc)*KCH + pch;                                         \
        const float* plane = x0 + ((size_t)(b*C + gc))*HW;                     \
        const float* kr = g_kern + ((size_t)(b*C + gc))*KK;                    \
        _Pragma("unroll")                                                      \
        for (int i = 0; i < 9; ++i) kv[i] = kr[i];                             \
        _Pragma("unroll")                                                      \
        for (int dr = 0; dr < 3; ++dr) {                                       \
            const int hh = h + dr - 1;                                         \
            if (hh < 0 || hh >= HH) {                                          \
                v4[dr].x = v4[dr].y = v4[dr].z = v4[dr].w = 0.f;               \
                vl[dr] = 0.f; vr[dr] = 0.f;                                    \
            } else {                                                           \
                const float* row = plane + hh*WW + w0;                         \
                v4[dr] = *(const float4*)row;                                  \
                vl[dr] = (w0 > 0)      ? row[-1] : 0.f;                        \
                vr[dr] = (w0 < WW - 4) ? row[4]  : 0.f;                        \
            }                                                                  \
        }                                                                      \
    } while (0)

#define COMPUTE() do {                                                         \
        float a0 = 0.f, a1 = 0.f, a2 = 0.f, a3 = 0.f;                          \
        _Pragma("unroll")                                                      \
        for (int dr = 0; dr < 3; ++dr) {                                       \
            const float k0 = kv[dr*3+0], k1 = kv[dr*3+1], k2 = kv[dr*3+2];     \
            a0 += k0*vl[dr]   + k1*v4[dr].x + k2*v4[dr].y;                     \
            a1 += k0*v4[dr].x + k1*v4[dr].y + k2*v4[dr].z;                     \
            a2 += k0*v4[dr].y + k1*v4[dr].z + k2*v4[dr].w;                     \
            a3 += k0*v4[dr].z + k1*v4[dr].w + k2*vr[dr];                       \
        }                                                                      \
        __half2 h01 = __floats2half2_rn(lrelu(a0), lrelu(a1));                 \
        __half2 h23 = __floats2half2_rn(lrelu(a2), lrelu(a3));                 \
        pk.x = *(uint32_t*)&h01;                                               \
        pk.y = *(uint32_t*)&h23;                                               \
    } while (0)

    // ---- chunk 0 producer (overlaps sA cp.async) ----
    LOADX(0);
    COMPUTE();
    asm volatile("cp.async.wait_group 0;");   // sA done (visibility via sync below)

    #pragma unroll
    for (int c = 0; c < NCHUNK; ++c) {
        const int st = c & 1;
        // STS current chunk's mid tile
        *(uint2*)((__half*)sB[st] + pch*SBST + (tid & 15)*4) = pk;
        __syncthreads();

        if (c + 1 < NCHUNK) LOADX(c + 1);   // prefetch (consumed after MMAs)

        // ---- MMA on chunk c ----
        uint32_t af[2][4];
        const int arow = lane & 15;
        const int au   = c*2 + (lane >> 4);       // logical A 16B unit
        #pragma unroll
        for (int mt = 0; mt < 2; ++mt) {
            const int r = wm0 + mt*16 + arow;
            ldmatrix_x4(af[mt], &sA[r*128 + ((au ^ (r & 7)) << 3)]);
        }

        uint32_t bf[4][2];
        const int brow = lane & 15;
        #pragma unroll
        for (int nt = 0; nt < 4; ++nt)
            ldmatrix_x2_t(bf[nt], (__half*)sB[st] + brow*SBST + wn0 + nt*8);

        #pragma unroll
        for (int mt = 0; mt < 2; ++mt)
            #pragma unroll
            for (int nt = 0; nt < 4; ++nt)
                mma_f16(d[mt][nt], af[mt], bf[nt]);

        if (c + 1 < NCHUNK) COMPUTE();      // dwconv for chunk c+1

        __syncthreads();                    // stage st safe to rewrite at c+2
    }

    // ---- fused epilogue: bias + x0*att residual ----
    const int pix0 = h * WW + px0;
    #pragma unroll
    for (int mt = 0; mt < 2; ++mt) {
        #pragma unroll
        for (int hf = 0; hf < 2; ++hf) {
            const int o  = wm0 + mt*16 + g + hf*8;
            const float bo = bias[o];
            const float at = g_att[b*C + o];
            const float* __restrict__ xrow = x0  + ((size_t)(b*C + o))*HW + pix0;
            float* __restrict__       orow = out + ((size_t)(b*C + o))*HW + pix0;
            #pragma unroll
            for (int nt = 0; nt < 4; ++nt) {
                const int cc2 = wn0 + nt*8 + 2*tg;
                float2 xv = *(const float2*)(xrow + cc2);
                float2 ov;
                ov.x = d[mt][nt][hf*2 + 0] + bo + xv.x*at;
                ov.y = d[mt][nt][hf*2 + 1] + bo + xv.y*at;
                *(float2*)(orow + cc2) = ov;
            }
        }
    }
}

// ---------------------------------------------------------------------------
extern "C" void kernel_launch(void* const* d_in, const int* in_sizes, int n_in,
                              void* d_out, int out_size)
{
    const float* x0    = (const float*)d_in[0];
    const float* deg   = (const float*)d_in[1];
    const float* w1    = (const float*)d_in[2];
    const float* w2    = (const float*)d_in[3];
    const float* convw = (const float*)d_in[4];
    const float* convb = (const float*)d_in[5];
    const float* caw1  = (const float*)d_in[6];
    const float* caw2  = (const float*)d_in[7];
    float* out = (float*)d_out;

    prep1_kernel<<<144, 256>>>(deg, w1, caw1);
    prep1b_kernel<<<B, 256>>>(caw2, convw);
    prep2_kernel<<<(B*C*KK)/8, 256>>>(w2);
    fused_kernel<<<dim3(HH*2, B), 256>>>(convb, x0, out);
}